// round 7
// baseline (speedup 1.0000x reference)
#include <cuda_runtime.h>

#define GAMMA_ 10.0f
#define EPS_   1e-6f

constexpr int Cn = 1000;  // classes
constexpr int Bn = 128;   // batch
constexpr int SPLITK = 4;

// ---------------- device scratch ----------------
__device__ float g_U[128 * 1024];          // gathered target columns W[:,t_i] (fp32)
__device__ float g_npart[16][1024];        // norm partials: idx = z*4 + rowhalf
__device__ float g_P[SPLITK][256][1024];   // split-K slabs: rows 0..127 logits, 128..255 gram

// ---------------- k1: gather only ----------------
__global__ __launch_bounds__(256) void k1_gather(const float* __restrict__ W,
                                                 const int* __restrict__ targets) {
    const int i = blockIdx.x >> 2;
    const int k = (blockIdx.x & 3) * 256 + threadIdx.x;
    const int t = targets[i];
    g_U[i * 1024 + k] = W[k * Cn + t];
}

// ---------------- k2: tf32 mma.sync GEMM, CTA 128x64, 8 warps, split-K=4 ----
// blockIdx.y: 0 = A rows (logits), 1 = U rows (gram), 2 = norm-partial lane
constexpr int PA = 36;   // (gid*36 + q) % 32 = gid*4+q : bijective -> conflict-free A frags
constexpr int PB = 72;   // (q*72 + gid) % 32 = q*8+gid : bijective -> conflict-free B frags
constexpr int AS_WORDS = 2 * 128 * PA;              // per-buffer-pair A tile words
constexpr int SMEM_K2 = (AS_WORDS + 2 * 32 * PB) * 4;  // 36864 + 18432 = 55296 bytes

extern __shared__ unsigned smem_k2[];

__global__ __launch_bounds__(256) void k2_gemm(const float* __restrict__ A,
                                               const float* __restrict__ W,
                                               float* __restrict__ out) {
    const int tid = threadIdx.x;
    const int mb = blockIdx.y;

    if (mb == 2) {
        // norm partials for this split-K slab (overlaps with GEMM blocks)
        const int item = blockIdx.x * 256 + tid;   // 0..4095
        const int c = item & 1023;
        const int h = item >> 10;                  // 0..3
        if (c < Cn) {
            const int r0 = blockIdx.z * 256 + h * 64;
            float acc = 0.0f;
#pragma unroll
            for (int j = 0; j < 64; ++j) {
                float w = W[(r0 + j) * Cn + c];
                acc = fmaf(w, w, acc);
            }
            g_npart[blockIdx.z * 4 + h][c] = acc;
        }
        if (blockIdx.x == 0 && blockIdx.z == 0 && tid == 0) out[0] = 0.0f;
        return;
    }

    // dynamic smem layout: As[2][128][PA] then Bs[2][32][PB]
    unsigned* AsBase = smem_k2;
    unsigned* BsBase = smem_k2 + AS_WORDS;
#define AS(bf, r, c) AsBase[(bf) * 128 * PA + (r) * PA + (c)]
#define BS(bf, r, c) BsBase[(bf) * 32 * PB + (r) * PB + (c)]

    const int lane = tid & 31, wid = tid >> 5;
    const int wm = wid & 3, wn = wid >> 2;           // warp grid 4 x 2
    const int n0 = blockIdx.x * 64;
    const int kb = blockIdx.z;
    const float* Asrc = mb ? g_U : A;                // 128 rows each
    const int kbase = kb * 256;

    float acc[2][4][4];
#pragma unroll
    for (int i = 0; i < 2; ++i)
#pragma unroll
        for (int j = 0; j < 4; ++j)
#pragma unroll
            for (int k = 0; k < 4; ++k) acc[i][j][k] = 0.f;

    uint4 pa[4], pb[2];
    auto ldchunk = [&](int kc) {
        const int k0 = kbase + kc * 32;
#pragma unroll
        for (int p = 0; p < 4; ++p) {
            int i = tid + 256 * p;                   // 1024 granules
            int row = i >> 3, kq = i & 7;
            pa[p] = *(const uint4*)(Asrc + row * 1024 + k0 + kq * 4);
        }
#pragma unroll
        for (int p = 0; p < 2; ++p) {
            int i = tid + 256 * p;                   // 512 granules
            int r = i >> 4, nq = i & 15;
            int gc = n0 + nq * 4;
            pb[p] = (gc < Cn) ? *(const uint4*)(W + (k0 + r) * Cn + gc)
                              : make_uint4(0u, 0u, 0u, 0u);
        }
    };
    auto stchunk = [&](int bf) {
#pragma unroll
        for (int p = 0; p < 4; ++p) {
            int i = tid + 256 * p;
            int row = i >> 3, kq = i & 7;
            *(uint4*)&AS(bf, row, kq * 4) = pa[p];
        }
#pragma unroll
        for (int p = 0; p < 2; ++p) {
            int i = tid + 256 * p;
            int r = i >> 4, nq = i & 15;
            *(uint4*)&BS(bf, r, nq * 4) = pb[p];
        }
    };

    ldchunk(0);
    stchunk(0);
    __syncthreads();

    for (int ch = 0; ch < 8; ++ch) {
        if (ch < 7) ldchunk(ch + 1);
        const int bf = ch & 1;
        const int gid = lane >> 2, q = lane & 3;
#pragma unroll
        for (int ks = 0; ks < 4; ++ks) {
            const int col = ks * 8 + q;
            unsigned a[2][4], b[4][2];
#pragma unroll
            for (int mf = 0; mf < 2; ++mf) {
                int r = wm * 32 + mf * 16 + gid;
                a[mf][0] = AS(bf, r, col);
                a[mf][1] = AS(bf, r + 8, col);
                a[mf][2] = AS(bf, r, col + 4);
                a[mf][3] = AS(bf, r + 8, col + 4);
            }
#pragma unroll
            for (int nf = 0; nf < 4; ++nf) {
                int nn = wn * 32 + nf * 8 + gid;
                b[nf][0] = BS(bf, col, nn);
                b[nf][1] = BS(bf, col + 4, nn);
            }
#pragma unroll
            for (int mf = 0; mf < 2; ++mf)
#pragma unroll
                for (int nf = 0; nf < 4; ++nf)
                    asm volatile(
                        "mma.sync.aligned.m16n8k8.row.col.f32.tf32.tf32.f32 "
                        "{%0,%1,%2,%3},{%4,%5,%6,%7},{%8,%9},{%0,%1,%2,%3};"
                        : "+f"(acc[mf][nf][0]), "+f"(acc[mf][nf][1]),
                          "+f"(acc[mf][nf][2]), "+f"(acc[mf][nf][3])
                        : "r"(a[mf][0]), "r"(a[mf][1]), "r"(a[mf][2]), "r"(a[mf][3]),
                          "r"(b[nf][0]), "r"(b[nf][1]));
        }
        if (ch < 7) {
            __syncthreads();
            stchunk((ch + 1) & 1);
            __syncthreads();
        }
    }

    // epilogue: plain stores into this split-K slab
    const int m0 = mb * 128, gid = lane >> 2, q = lane & 3;
#pragma unroll
    for (int mf = 0; mf < 2; ++mf) {
        int row = m0 + wm * 32 + mf * 16 + gid;
#pragma unroll
        for (int nf = 0; nf < 4; ++nf) {
            int coln = n0 + wn * 32 + nf * 8 + 2 * q;
            *(float2*)&g_P[kb][row][coln]     = make_float2(acc[mf][nf][0], acc[mf][nf][1]);
            *(float2*)&g_P[kb][row + 8][coln] = make_float2(acc[mf][nf][2], acc[mf][nf][3]);
        }
    }
#undef AS
#undef BS
}

// ---------------- k3: per-row max violation, mean into out ----------------
__global__ __launch_bounds__(1024) void k3_loss(const float* __restrict__ bvec,
                                                const int* __restrict__ targets,
                                                float* __restrict__ out) {
    const int i = blockIdx.x;
    const int c = threadIdx.x;
    const int t = targets[i];
    __shared__ float s_corr, s_nt;
    __shared__ float red[32];

    float nc = 0.0f;
    if (c < Cn) {
#pragma unroll
        for (int p = 0; p < 16; ++p) nc += g_npart[p][c];
    }

    if (c == 0) {
        float sc = bvec[t], nt = 0.0f;
#pragma unroll
        for (int s = 0; s < SPLITK; ++s) sc += g_P[s][i][t];
#pragma unroll
        for (int p = 0; p < 16; ++p) nt += g_npart[p][t];
        s_corr = sc;
        s_nt = nt;
    }
    __syncthreads();

    float v = 0.0f;
    if (c < Cn && c != t) {
        float lg = bvec[c], gr = 0.0f;
#pragma unroll
        for (int s = 0; s < SPLITK; ++s) {
            lg += g_P[s][i][c];
            gr += g_P[s][i + 128][c];
        }
        float ss = nc + s_nt - 2.0f * gr;
        float dn = sqrtf(ss + EPS_) + EPS_;
        v = fmaxf(0.0f, GAMMA_ + (lg - s_corr) / dn);
    }
#pragma unroll
    for (int o = 16; o; o >>= 1) v = fmaxf(v, __shfl_xor_sync(~0u, v, o));
    if ((c & 31) == 0) red[c >> 5] = v;
    __syncthreads();
    if (c < 32) {
        float r = red[c];
#pragma unroll
        for (int o = 16; o; o >>= 1) r = fmaxf(r, __shfl_xor_sync(~0u, r, o));
        if (c == 0) atomicAdd(out, r * (1.0f / 128.0f));
    }
}

// ---------------- launch ----------------
extern "C" void kernel_launch(void* const* d_in, const int* in_sizes, int n_in,
                              void* d_out, int out_size) {
    const float* A = (const float*)d_in[0];        // [128,1024]
    const float* W = (const float*)d_in[1];        // [1024,1000]
    const float* b = (const float*)d_in[2];        // [1000]
    const int* targets = (const int*)d_in[3];      // [128]
    float* out = (float*)d_out;

    static int smem_set = 0;
    if (!smem_set) {
        cudaFuncSetAttribute(k2_gemm, cudaFuncAttributeMaxDynamicSharedMemorySize, SMEM_K2);
        smem_set = 1;
    }

    k1_gather<<<512, 256>>>(W, targets);
    k2_gemm<<<dim3(16, 3, SPLITK), 256, SMEM_K2>>>(A, W, out);
    k3_loss<<<Bn, 1024>>>(b, targets, out);
}